// round 1
// baseline (speedup 1.0000x reference)
#include <cuda_runtime.h>
#include <math.h>

#define NSTACK 12
#define ZEROOFF 0.001f
#define EPSV 1e-8f

// Fixed problem shapes (B=32, T=256) for scratch sizing.
__device__ float g_norms[2];            // [0]=||latch_enable||, [1]=||should_pop||
__device__ float g_interp[32 * 256];
__device__ float g_coef[32 * 256 * 49]; // per (b,t): a[12], c[12], e[12], q[12], pop

// ---------------------------------------------------------------------------
// Pair block-reduce (sum) for 256-thread blocks.
// ---------------------------------------------------------------------------
__device__ __forceinline__ void block_reduce2(float& a, float& b) {
    #pragma unroll
    for (int o = 16; o > 0; o >>= 1) {
        a += __shfl_xor_sync(0xffffffffu, a, o);
        b += __shfl_xor_sync(0xffffffffu, b, o);
    }
    __shared__ float sa[32], sb[32];
    int lane = threadIdx.x & 31;
    int w = threadIdx.x >> 5;
    int nw = (blockDim.x + 31) >> 5;
    if (lane == 0) { sa[w] = a; sb[w] = b; }
    __syncthreads();
    if (w == 0) {
        a = (lane < nw) ? sa[lane] : 0.0f;
        b = (lane < nw) ? sb[lane] : 0.0f;
        #pragma unroll
        for (int o = 16; o > 0; o >>= 1) {
            a += __shfl_xor_sync(0xffffffffu, a, o);
            b += __shfl_xor_sync(0xffffffffu, b, o);
        }
        if (lane == 0) { sa[0] = a; sb[0] = b; }
    }
    __syncthreads();
    a = sa[0];
    b = sb[0];
}

// ---------------------------------------------------------------------------
// K0: norms of latch_enable and should_pop (constants for the whole run).
// ---------------------------------------------------------------------------
__global__ void k0_norms(const float* __restrict__ le, const float* __restrict__ sp, int V) {
    float a = 0.f, b = 0.f;
    for (int v = threadIdx.x; v < V; v += blockDim.x) {
        float l = le[v], s = sp[v];
        a += l * l;
        b += s * s;
    }
    block_reduce2(a, b);
    if (threadIdx.x == 0) {
        g_norms[0] = sqrtf(a);
        g_norms[1] = sqrtf(b);
    }
}

// ---------------------------------------------------------------------------
// K1: interp[b,t] = cos(latch_enable, x[b,t]).  One block per (b,t).
// ---------------------------------------------------------------------------
__global__ void k1_interp(const float* __restrict__ x, const float* __restrict__ le, int V) {
    int bt = blockIdx.x;
    const float* xp = x + (size_t)bt * V;
    float d = 0.f, n = 0.f;
    for (int v = threadIdx.x; v < V; v += blockDim.x) {
        float xv = xp[v];
        d += le[v] * xv;
        n += xv * xv;
    }
    block_reduce2(d, n);
    if (threadIdx.x == 0) {
        float nle = fmaxf(g_norms[0], EPSV);
        float nx = fmaxf(sqrtf(n), EPSV);
        g_interp[bt] = d / (nle * nx);
    }
}

// ---------------------------------------------------------------------------
// K2: latch scan, parallel over (b,v); writes latches output [B,T,V].
// grid (V/256, B), block 256; dyn smem = T floats for interp row.
// ---------------------------------------------------------------------------
__global__ void k2_latch(const float* __restrict__ x, const float* __restrict__ latch0,
                         float* __restrict__ latches, int T, int V) {
    extern __shared__ float s_i[];
    int b = blockIdx.y;
    int v = blockIdx.x * blockDim.x + threadIdx.x;
    for (int t = threadIdx.x; t < T; t += blockDim.x) s_i[t] = g_interp[b * T + t];
    __syncthreads();
    float latch = latch0[(size_t)b * V + v];
    const float* xp = x + (size_t)b * T * V + v;
    float* lp = latches + (size_t)b * T * V + v;
    #pragma unroll 4
    for (int t = 0; t < T; t++) {
        float i = s_i[t];
        float xv = xp[(size_t)t * V];
        latch = (1.0f - i) * latch + i * xv;
        lp[(size_t)t * V] = latch;
    }
}

// ---------------------------------------------------------------------------
// K3: pop[b,t] = elu(cos(should_pop, latch_{t-1})).  One block per (b,t).
// ---------------------------------------------------------------------------
__global__ void k3_pops(const float* __restrict__ latches, const float* __restrict__ latch0,
                        const float* __restrict__ sp, float* __restrict__ pops, int T, int V) {
    int bt = blockIdx.x;
    int b = bt / T;
    int t = bt - b * T;
    const float* lp = (t == 0) ? (latch0 + (size_t)b * V)
                               : (latches + (size_t)(bt - 1) * V);
    float d = 0.f, n = 0.f;
    for (int v = threadIdx.x; v < V; v += blockDim.x) {
        float l = lp[v];
        d += sp[v] * l;
        n += l * l;
    }
    block_reduce2(d, n);
    if (threadIdx.x == 0) {
        float nsp = fmaxf(g_norms[1], EPSV);
        float nl = fmaxf(sqrtf(n), EPSV);
        float c = d / (nsp * nl);
        pops[bt] = (c > 0.0f) ? c : expm1f(c);
    }
}

// ---------------------------------------------------------------------------
// K4: pointer scan (serial over T), one warp per batch. Emits per-step
// affine coefficients for the stack update + new_ptr + pop into g_coef.
//   new_stack[n,v] = a[n]*stack[n,v] + (c[n]*x[v] + e[n])
// ---------------------------------------------------------------------------
__global__ void k4_ptr(const float* __restrict__ pops, const float* __restrict__ sharp_ptr, int T) {
    const unsigned FULL = 0xffffffffu;
    int b = blockIdx.x;
    int lane = threadIdx.x;
    bool active = lane < NSTACK;
    float sharp = sharp_ptr[0];
    float ptr = (lane == 0) ? 1.0f : 0.0f;
    float* cbase = g_coef + (size_t)b * T * 49;
    int src_push = (lane + NSTACK - 1) % NSTACK; // ptr[n-1]  (roll +1)
    int src_pop = (lane + 1) % NSTACK;           // ptr[n+1]  (roll -1)
    for (int t = 0; t < T; t++) {
        float pop = pops[b * T + t];
        float push = 1.0f - pop;
        float ptr_push = __shfl_sync(FULL, ptr, src_push);
        float ptr_pop = __shfl_sync(FULL, ptr, src_pop);
        float a = push * (1.0f - ptr_push) + pop * (1.0f - ptr);
        float c = push * ptr_push;
        float e = pop * (ZEROOFF * ptr);
        float mix = push * ptr_push + pop * ptr_pop;
        float pm = fmaxf(mix, 0.0f);
        float pw;
        if (sharp == 5.0f) {
            float p2 = pm * pm;
            pw = p2 * p2 * pm;
        } else {
            pw = powf(pm, sharp);
        }
        float s = active ? pw : 0.0f;
        #pragma unroll
        for (int o = 16; o > 0; o >>= 1) s += __shfl_xor_sync(FULL, s, o);
        float q = pw / (s + EPSV);
        float* cf = cbase + (size_t)t * 49;
        if (active) {
            cf[lane] = a;
            cf[12 + lane] = c;
            cf[24 + lane] = e;
            cf[36 + lane] = q;
        }
        if (lane == 0) cf[48] = pop;
        ptr = q;
    }
}

// ---------------------------------------------------------------------------
// K5: stack scan, parallel over (b,v); 12-deep stack in registers,
// coefficients broadcast from smem. VPT=2 columns per thread.
// grid (V/512, B), block 256, dyn smem = T*49 floats (~50 KB).
// ---------------------------------------------------------------------------
__global__ void k5_stack(const float* __restrict__ x, float* __restrict__ outs,
                         float* __restrict__ tops, int T, int V) {
    extern __shared__ float s_c[];
    int b = blockIdx.y;
    const float* cbase = g_coef + (size_t)b * T * 49;
    for (int i = threadIdx.x; i < T * 49; i += blockDim.x) s_c[i] = cbase[i];
    __syncthreads();

    const int VPT = 2;
    int stride = gridDim.x * blockDim.x; // = V / VPT
    int v0 = blockIdx.x * blockDim.x + threadIdx.x;

    float st[VPT][NSTACK];
    #pragma unroll
    for (int k = 0; k < VPT; k++)
        #pragma unroll
        for (int n = 0; n < NSTACK; n++) st[k][n] = ZEROOFF;

    const float* xb = x + (size_t)b * T * V;
    float* ob = outs + (size_t)b * T * V;
    float* tb = tops + (size_t)b * T * V;

    for (int t = 0; t < T; t++) {
        const float* cf = s_c + t * 49;
        float pop = cf[48];
        #pragma unroll
        for (int k = 0; k < VPT; k++) {
            int v = v0 + k * stride;
            float inp = xb[(size_t)t * V + v];
            float top = 0.0f;
            #pragma unroll
            for (int n = 0; n < NSTACK; n++) {
                float w = fmaf(cf[12 + n], inp, cf[24 + n]);
                st[k][n] = fmaf(cf[n], st[k][n], w);
                top = fmaf(st[k][n], cf[36 + n], top);
            }
            ob[(size_t)t * V + v] = pop * top;
            tb[(size_t)t * V + v] = top;
        }
    }
}

// ---------------------------------------------------------------------------
// Launch: K0 -> K1 -> K2 -> K3 -> K4 -> K5 on the default stream.
// Output layout: [outs (B*T*V)] [latches (B*T*V)] [pops (B*T)] [tops (B*T*V)]
// ---------------------------------------------------------------------------
extern "C" void kernel_launch(void* const* d_in, const int* in_sizes, int n_in,
                              void* d_out, int out_size) {
    const float* x = (const float*)d_in[0];
    const float* sp = (const float*)d_in[1];
    const float* shp = (const float*)d_in[2];
    const float* le = (const float*)d_in[3];
    const float* l0 = (const float*)d_in[4];

    int V = in_sizes[1];
    int B = in_sizes[4] / V;
    int T = in_sizes[0] / in_sizes[4];

    float* out = (float*)d_out;
    size_t btv = (size_t)B * T * V;
    float* outs = out;
    float* latches = out + btv;
    float* pops = out + 2 * btv;
    float* tops = out + 2 * btv + (size_t)B * T;

    // K5 needs > 48KB dynamic smem.
    static bool attr_set = false;
    if (!attr_set) {
        cudaFuncSetAttribute(k5_stack, cudaFuncAttributeMaxDynamicSharedMemorySize,
                             49 * 256 * (int)sizeof(float) + 256);
        attr_set = true;
    }

    k0_norms<<<1, 256>>>(le, sp, V);
    k1_interp<<<B * T, 256>>>(x, le, V);
    dim3 g2(V / 256, B);
    k2_latch<<<g2, 256, T * sizeof(float)>>>(x, l0, latches, T, V);
    k3_pops<<<B * T, 256>>>(latches, l0, sp, pops, T, V);
    k4_ptr<<<B, 32>>>(pops, shp, T);
    dim3 g5(V / 512, B);
    k5_stack<<<g5, 256, T * 49 * sizeof(float)>>>(x, outs, tops, T, V);
}

// round 2
// speedup vs baseline: 1.2824x; 1.2824x over previous
#include <cuda_runtime.h>
#include <math.h>

#define NSTACK 12
#define ZEROOFF 0.001f
#define EPSV 1e-8f
#define CSTRIDE 52   // padded per-step coefficient record (16B-aligned sections)

// Fixed shapes (B=32, T=256, V=2048) for scratch sizing.
__device__ float g_norms[2];                  // [0]=||latch_enable||, [1]=||should_pop||
__device__ float g_interp[32 * 256];
__device__ float g_coef[32 * 256 * CSTRIDE];  // per (b,t): a[0:12] c[12:24] e[24:36] q[36:48] pop[48]

// ---------------------------------------------------------------------------
// K0: norms of latch_enable and should_pop.
// ---------------------------------------------------------------------------
__global__ void k0_norms(const float* __restrict__ le, const float* __restrict__ sp, int V) {
    float a = 0.f, b = 0.f;
    int lane = threadIdx.x & 31;
    const float4* le4 = (const float4*)le;
    const float4* sp4 = (const float4*)sp;
    for (int i = threadIdx.x; i < V / 4; i += blockDim.x) {
        float4 l = le4[i], s = sp4[i];
        a += l.x * l.x + l.y * l.y + l.z * l.z + l.w * l.w;
        b += s.x * s.x + s.y * s.y + s.z * s.z + s.w * s.w;
    }
    #pragma unroll
    for (int o = 16; o > 0; o >>= 1) {
        a += __shfl_xor_sync(0xffffffffu, a, o);
        b += __shfl_xor_sync(0xffffffffu, b, o);
    }
    __shared__ float sa[32], sb[32];
    int w = threadIdx.x >> 5;
    if (lane == 0) { sa[w] = a; sb[w] = b; }
    __syncthreads();
    if (threadIdx.x == 0) {
        float ta = 0.f, tb = 0.f;
        for (int i = 0; i < (int)(blockDim.x >> 5); i++) { ta += sa[i]; tb += sb[i]; }
        g_norms[0] = sqrtf(ta);
        g_norms[1] = sqrtf(tb);
    }
}

// ---------------------------------------------------------------------------
// K1: interp[b,t] = cos(latch_enable, x[b,t]).  One WARP per (b,t) row.
// block = 256 (8 warps), grid = B*T/8.
// ---------------------------------------------------------------------------
__global__ void k1_interp(const float* __restrict__ x, const float* __restrict__ le, int V) {
    int row = blockIdx.x * 8 + (threadIdx.x >> 5);
    int lane = threadIdx.x & 31;
    const float4* xp = (const float4*)(x + (size_t)row * V);
    const float4* le4 = (const float4*)le;
    float d = 0.f, n = 0.f;
    for (int i = lane; i < V / 4; i += 32) {
        float4 xv = xp[i], l = le4[i];
        d += l.x * xv.x + l.y * xv.y + l.z * xv.z + l.w * xv.w;
        n += xv.x * xv.x + xv.y * xv.y + xv.z * xv.z + xv.w * xv.w;
    }
    #pragma unroll
    for (int o = 16; o > 0; o >>= 1) {
        d += __shfl_xor_sync(0xffffffffu, d, o);
        n += __shfl_xor_sync(0xffffffffu, n, o);
    }
    if (lane == 0) {
        float nle = fmaxf(g_norms[0], EPSV);
        float nx = fmaxf(sqrtf(n), EPSV);
        g_interp[row] = d / (nle * nx);
    }
}

// ---------------------------------------------------------------------------
// K2: latch scan, parallel over (b,v) in float4 units; writes latches [B,T,V].
// grid (V/4/256, B), block 256; dyn smem = T floats.
// ---------------------------------------------------------------------------
__global__ void k2_latch(const float* __restrict__ x, const float* __restrict__ latch0,
                         float* __restrict__ latches, int T, int V) {
    extern __shared__ float s_i[];
    int b = blockIdx.y;
    int v4 = blockIdx.x * blockDim.x + threadIdx.x;
    for (int t = threadIdx.x; t < T; t += blockDim.x) s_i[t] = g_interp[b * T + t];
    __syncthreads();
    int stride4 = V >> 2;
    float4 latch = ((const float4*)(latch0 + (size_t)b * V))[v4];
    const float4* xp = (const float4*)(x + (size_t)b * T * V) + v4;
    float4* lp = (float4*)(latches + (size_t)b * T * V) + v4;
    #pragma unroll 4
    for (int t = 0; t < T; t++) {
        float i = s_i[t];
        float4 xv = xp[(size_t)t * stride4];
        latch.x = fmaf(i, xv.x - latch.x, latch.x);
        latch.y = fmaf(i, xv.y - latch.y, latch.y);
        latch.z = fmaf(i, xv.z - latch.z, latch.z);
        latch.w = fmaf(i, xv.w - latch.w, latch.w);
        lp[(size_t)t * stride4] = latch;
    }
}

// ---------------------------------------------------------------------------
// K3: pop[b,t] = elu(cos(should_pop, latch_{t-1})).  One WARP per (b,t).
// block = 256 (8 warps), grid = B*T/8.
// ---------------------------------------------------------------------------
__global__ void k3_pops(const float* __restrict__ latches, const float* __restrict__ latch0,
                        const float* __restrict__ sp, float* __restrict__ pops, int T, int V) {
    int bt = blockIdx.x * 8 + (threadIdx.x >> 5);
    int lane = threadIdx.x & 31;
    int b = bt / T;
    int t = bt - b * T;
    const float* lrow = (t == 0) ? (latch0 + (size_t)b * V)
                                 : (latches + (size_t)(bt - 1) * V);
    const float4* lp = (const float4*)lrow;
    const float4* sp4 = (const float4*)sp;
    float d = 0.f, n = 0.f;
    for (int i = lane; i < V / 4; i += 32) {
        float4 l = lp[i], s = sp4[i];
        d += s.x * l.x + s.y * l.y + s.z * l.z + s.w * l.w;
        n += l.x * l.x + l.y * l.y + l.z * l.z + l.w * l.w;
    }
    #pragma unroll
    for (int o = 16; o > 0; o >>= 1) {
        d += __shfl_xor_sync(0xffffffffu, d, o);
        n += __shfl_xor_sync(0xffffffffu, n, o);
    }
    if (lane == 0) {
        float nsp = fmaxf(g_norms[1], EPSV);
        float nl = fmaxf(sqrtf(n), EPSV);
        float c = d / (nsp * nl);
        pops[bt] = (c > 0.0f) ? c : expm1f(c);
    }
}

// ---------------------------------------------------------------------------
// K4: pointer scan (serial over T), one warp per batch. pops preloaded to smem.
// Emits per-step affine coefficients: new_stack[n,v] = a[n]*stack[n,v] + c[n]*x[v] + e[n]
// ---------------------------------------------------------------------------
__global__ void k4_ptr(const float* __restrict__ pops, const float* __restrict__ sharp_ptr, int T) {
    const unsigned FULL = 0xffffffffu;
    __shared__ float s_pop[256];
    int b = blockIdx.x;
    int lane = threadIdx.x;
    for (int i = lane; i < T; i += 32) s_pop[i] = pops[b * T + i];
    __syncwarp();
    bool active = lane < NSTACK;
    float sharp = sharp_ptr[0];
    bool fast5 = (sharp == 5.0f);
    float ptr = (lane == 0) ? 1.0f : 0.0f;
    float* cbase = g_coef + (size_t)b * T * CSTRIDE;
    int src_push = (lane + NSTACK - 1) % NSTACK;
    int src_pop = (lane + 1) % NSTACK;
    for (int t = 0; t < T; t++) {
        float pop = s_pop[t];
        float push = 1.0f - pop;
        float ptr_push = __shfl_sync(FULL, ptr, src_push);
        float ptr_pop = __shfl_sync(FULL, ptr, src_pop);
        float a = push * (1.0f - ptr_push) + pop * (1.0f - ptr);
        float c = push * ptr_push;
        float e = pop * (ZEROOFF * ptr);
        float mix = push * ptr_push + pop * ptr_pop;
        float pm = fmaxf(mix, 0.0f);
        float pw;
        if (fast5) {
            float p2 = pm * pm;
            pw = p2 * p2 * pm;
        } else {
            pw = powf(pm, sharp);
        }
        float s = active ? pw : 0.0f;
        // state lives in lanes 0..11 -> 16-lane butterfly suffices (lanes 12..15 are 0)
        #pragma unroll
        for (int o = 8; o > 0; o >>= 1) s += __shfl_xor_sync(FULL, s, o);
        float q = __fdividef(pw, s + EPSV);
        float* cf = cbase + (size_t)t * CSTRIDE;
        if (active) {
            cf[lane] = a;
            cf[12 + lane] = c;
            cf[24 + lane] = e;
            cf[36 + lane] = q;
        }
        if (lane == 0) cf[48] = pop;
        ptr = q;
    }
}

// ---------------------------------------------------------------------------
// K5: stack scan, parallel over (b,v); 12-deep stack in registers,
// coefficients via LDS.128 from smem. VPT=2, grid (V/512, B), block 256.
// ---------------------------------------------------------------------------
__global__ void k5_stack(const float* __restrict__ x, float* __restrict__ outs,
                         float* __restrict__ tops, int T, int V) {
    extern __shared__ float s_c[];
    int b = blockIdx.y;
    const float4* cg = (const float4*)(g_coef + (size_t)b * T * CSTRIDE);
    float4* cs = (float4*)s_c;
    for (int i = threadIdx.x; i < T * (CSTRIDE / 4); i += blockDim.x) cs[i] = cg[i];
    __syncthreads();

    const int VPT = 2;
    int stride = gridDim.x * blockDim.x; // = V / VPT
    int v0 = blockIdx.x * blockDim.x + threadIdx.x;

    float st[VPT][NSTACK];
    #pragma unroll
    for (int k = 0; k < VPT; k++)
        #pragma unroll
        for (int n = 0; n < NSTACK; n++) st[k][n] = ZEROOFF;

    const float* xb = x + (size_t)b * T * V;
    float* ob = outs + (size_t)b * T * V;
    float* tb = tops + (size_t)b * T * V;

    for (int t = 0; t < T; t++) {
        const float4* cf4 = (const float4*)(s_c + t * CSTRIDE);
        float a[12], c[12], e[12], q[12];
        *(float4*)&a[0] = cf4[0]; *(float4*)&a[4] = cf4[1]; *(float4*)&a[8] = cf4[2];
        *(float4*)&c[0] = cf4[3]; *(float4*)&c[4] = cf4[4]; *(float4*)&c[8] = cf4[5];
        *(float4*)&e[0] = cf4[6]; *(float4*)&e[4] = cf4[7]; *(float4*)&e[8] = cf4[8];
        *(float4*)&q[0] = cf4[9]; *(float4*)&q[4] = cf4[10]; *(float4*)&q[8] = cf4[11];
        float pop = s_c[t * CSTRIDE + 48];
        #pragma unroll
        for (int k = 0; k < VPT; k++) {
            int v = v0 + k * stride;
            float inp = xb[(size_t)t * V + v];
            float top = 0.0f;
            #pragma unroll
            for (int n = 0; n < NSTACK; n++) {
                float w = fmaf(c[n], inp, e[n]);
                st[k][n] = fmaf(a[n], st[k][n], w);
                top = fmaf(st[k][n], q[n], top);
            }
            ob[(size_t)t * V + v] = pop * top;
            tb[(size_t)t * V + v] = top;
        }
    }
}

// ---------------------------------------------------------------------------
// Launch. Output layout: [outs BTV][latches BTV][pops BT][tops BTV]
// ---------------------------------------------------------------------------
extern "C" void kernel_launch(void* const* d_in, const int* in_sizes, int n_in,
                              void* d_out, int out_size) {
    const float* x = (const float*)d_in[0];
    const float* sp = (const float*)d_in[1];
    const float* shp = (const float*)d_in[2];
    const float* le = (const float*)d_in[3];
    const float* l0 = (const float*)d_in[4];

    int V = in_sizes[1];
    int B = in_sizes[4] / V;
    int T = in_sizes[0] / in_sizes[4];

    float* out = (float*)d_out;
    size_t btv = (size_t)B * T * V;
    float* outs = out;
    float* latches = out + btv;
    float* pops = out + 2 * btv;
    float* tops = out + 2 * btv + (size_t)B * T;

    static bool attr_set = false;
    if (!attr_set) {
        cudaFuncSetAttribute(k5_stack, cudaFuncAttributeMaxDynamicSharedMemorySize,
                             CSTRIDE * 256 * (int)sizeof(float) + 256);
        attr_set = true;
    }

    k0_norms<<<1, 256>>>(le, sp, V);
    k1_interp<<<B * T / 8, 256>>>(x, le, V);
    dim3 g2(V / 4 / 256, B);
    k2_latch<<<g2, 256, T * sizeof(float)>>>(x, l0, latches, T, V);
    k3_pops<<<B * T / 8, 256>>>(latches, l0, sp, pops, T, V);
    k4_ptr<<<B, 32>>>(pops, shp, T);
    dim3 g5(V / 512, B);
    k5_stack<<<g5, 256, T * CSTRIDE * sizeof(float)>>>(x, outs, tops, T, V);
}

// round 4
// speedup vs baseline: 1.6013x; 1.2487x over previous
#include <cuda_runtime.h>
#include <math.h>

#define NSTACK 12
#define ZEROOFF 0.001f
#define EPSV 1e-8f
#define CSTRIDE 52   // padded per-step coefficient record

// Fixed shapes (B=32, T=256, V=2048) for scratch sizing.
__device__ float g_norms[2];                  // [0]=||latch_enable||, [1]=||should_pop||
__device__ float g_interp[32 * 256];
__device__ float g_coef[32 * 256 * CSTRIDE];  // per (b,t): a[0:12] c[12:24] e[24:36] q[36:48] pop[48]
__device__ float g_partd[32 * 4 * 256];       // per (b, blk, t): partial sp.latch_{t-1}
__device__ float g_partn[32 * 4 * 256];       // per (b, blk, t): partial ||latch_{t-1}||^2

__device__ __forceinline__ float dot4(float4 a, float4 b) {
    return a.x * b.x + a.y * b.y + a.z * b.z + a.w * b.w;
}

// ---------------------------------------------------------------------------
// K0: norms of latch_enable and should_pop.
// ---------------------------------------------------------------------------
__global__ void k0_norms(const float* __restrict__ le, const float* __restrict__ sp, int V) {
    float a = 0.f, b = 0.f;
    int lane = threadIdx.x & 31;
    const float4* le4 = (const float4*)le;
    const float4* sp4 = (const float4*)sp;
    for (int i = threadIdx.x; i < V / 4; i += blockDim.x) {
        float4 l = le4[i], s = sp4[i];
        a += dot4(l, l);
        b += dot4(s, s);
    }
    #pragma unroll
    for (int o = 16; o > 0; o >>= 1) {
        a += __shfl_xor_sync(0xffffffffu, a, o);
        b += __shfl_xor_sync(0xffffffffu, b, o);
    }
    __shared__ float sa[32], sb[32];
    int w = threadIdx.x >> 5;
    if (lane == 0) { sa[w] = a; sb[w] = b; }
    __syncthreads();
    if (threadIdx.x == 0) {
        float ta = 0.f, tb = 0.f;
        for (int i = 0; i < (int)(blockDim.x >> 5); i++) { ta += sa[i]; tb += sb[i]; }
        g_norms[0] = sqrtf(ta);
        g_norms[1] = sqrtf(tb);
    }
}

// ---------------------------------------------------------------------------
// K1: interp[b,t] = cos(latch_enable, x[b,t]).  One WARP per (b,t) row.
// Batched loads (MLP=8). block 256, grid = B*T/8.
// ---------------------------------------------------------------------------
__global__ void k1_interp(const float* __restrict__ x, const float* __restrict__ le, int V) {
    int row = blockIdx.x * 8 + (threadIdx.x >> 5);
    int lane = threadIdx.x & 31;
    const float4* xp = (const float4*)(x + (size_t)row * V);
    const float4* le4 = (const float4*)le;
    float d = 0.f, n = 0.f;
    // V/4 = 512 float4; 4 outer iters of 4 batched loads per lane.
    for (int i0 = lane; i0 < V / 4; i0 += 128) {
        float4 xv[4], l[4];
        #pragma unroll
        for (int j = 0; j < 4; j++) { xv[j] = xp[i0 + 32 * j]; l[j] = le4[i0 + 32 * j]; }
        #pragma unroll
        for (int j = 0; j < 4; j++) {
            d += dot4(l[j], xv[j]);
            n += dot4(xv[j], xv[j]);
        }
    }
    #pragma unroll
    for (int o = 16; o > 0; o >>= 1) {
        d += __shfl_xor_sync(0xffffffffu, d, o);
        n += __shfl_xor_sync(0xffffffffu, n, o);
    }
    if (lane == 0) {
        float nle = fmaxf(g_norms[0], EPSV);
        float nx = fmaxf(sqrtf(n), EPSV);
        g_interp[row] = d / (nle * nx);
    }
}

// ---------------------------------------------------------------------------
// K2: latch scan + fused pop-reduction partials.
// grid (4, B), block 128 (4 warps). Each thread owns one float4 column.
// Per step: update latch, write it, warp-reduce (sp.latch, ||latch||^2) into
// smem slot t+1 (slot k holds stats of latch_{k-1}, i.e. for pop[k]).
// ---------------------------------------------------------------------------
__global__ void k2_latch(const float* __restrict__ x, const float* __restrict__ latch0,
                         const float* __restrict__ sp, float* __restrict__ latches,
                         int T, int V) {
    __shared__ float s_i[256];
    __shared__ float s_wd[256][4];
    __shared__ float s_wn[256][4];
    int b = blockIdx.y;
    int tid = threadIdx.x;
    int lane = tid & 31;
    int w = tid >> 5;
    int v4 = blockIdx.x * blockDim.x + tid;   // 0..511
    int stride4 = V >> 2;                      // 512

    for (int t = tid; t < T; t += blockDim.x) s_i[t] = g_interp[b * T + t];
    __syncthreads();

    float4 sp4 = ((const float4*)sp)[v4];
    float4 latch = ((const float4*)(latch0 + (size_t)b * V))[v4];
    const float4* xp = (const float4*)(x + (size_t)b * T * V) + v4;
    float4* lp = (float4*)(latches + (size_t)b * T * V) + v4;

    // slot 0: stats of latch0 (for pop[0])
    {
        float d = dot4(sp4, latch);
        float n = dot4(latch, latch);
        #pragma unroll
        for (int o = 16; o > 0; o >>= 1) {
            d += __shfl_xor_sync(0xffffffffu, d, o);
            n += __shfl_xor_sync(0xffffffffu, n, o);
        }
        if (lane == 0) { s_wd[0][w] = d; s_wn[0][w] = n; }
    }

    for (int t0 = 0; t0 < T; t0 += 8) {
        float4 xs[8];
        #pragma unroll
        for (int j = 0; j < 8; j++) xs[j] = xp[(size_t)(t0 + j) * stride4];
        #pragma unroll
        for (int j = 0; j < 8; j++) {
            int t = t0 + j;
            float i = s_i[t];
            latch.x = fmaf(i, xs[j].x - latch.x, latch.x);
            latch.y = fmaf(i, xs[j].y - latch.y, latch.y);
            latch.z = fmaf(i, xs[j].z - latch.z, latch.z);
            latch.w = fmaf(i, xs[j].w - latch.w, latch.w);
            lp[(size_t)t * stride4] = latch;
            if (t < T - 1) {
                float d = dot4(sp4, latch);
                float n = dot4(latch, latch);
                #pragma unroll
                for (int o = 16; o > 0; o >>= 1) {
                    d += __shfl_xor_sync(0xffffffffu, d, o);
                    n += __shfl_xor_sync(0xffffffffu, n, o);
                }
                if (lane == 0) { s_wd[t + 1][w] = d; s_wn[t + 1][w] = n; }
            }
        }
    }
    __syncthreads();
    int pbase = (b * 4 + blockIdx.x) * T;
    for (int t = tid; t < T; t += blockDim.x) {
        g_partd[pbase + t] = s_wd[t][0] + s_wd[t][1] + s_wd[t][2] + s_wd[t][3];
        g_partn[pbase + t] = s_wn[t][0] + s_wn[t][1] + s_wn[t][2] + s_wn[t][3];
    }
}

// ---------------------------------------------------------------------------
// K3b: finalize pop[b,t] = elu(cos) from the 4 per-block partials.
// ---------------------------------------------------------------------------
__global__ void k3b_pops(float* __restrict__ pops, int T) {
    int bt = blockIdx.x * blockDim.x + threadIdx.x;
    int b = bt / T;
    int t = bt - b * T;
    float d = 0.f, n = 0.f;
    #pragma unroll
    for (int blk = 0; blk < 4; blk++) {
        d += g_partd[(b * 4 + blk) * T + t];
        n += g_partn[(b * 4 + blk) * T + t];
    }
    float nsp = fmaxf(g_norms[1], EPSV);
    float nl = fmaxf(sqrtf(n), EPSV);
    float c = d / (nsp * nl);
    pops[bt] = (c > 0.0f) ? c : expm1f(c);
}

// ---------------------------------------------------------------------------
// K4: pointer scan (serial over T), one warp per batch; pops in smem;
// 16-lane butterfly reduce (state only in lanes 0..11).
// ---------------------------------------------------------------------------
__global__ void k4_ptr(const float* __restrict__ pops, const float* __restrict__ sharp_ptr, int T) {
    const unsigned FULL = 0xffffffffu;
    __shared__ float s_pop[256];
    int b = blockIdx.x;
    int lane = threadIdx.x;
    for (int i = lane; i < T; i += 32) s_pop[i] = pops[b * T + i];
    __syncwarp();
    bool active = lane < NSTACK;
    float sharp = sharp_ptr[0];
    bool fast5 = (sharp == 5.0f);
    float ptr = (lane == 0) ? 1.0f : 0.0f;
    float* cbase = g_coef + (size_t)b * T * CSTRIDE;
    int src_push = (lane + NSTACK - 1) % NSTACK;
    int src_pop = (lane + 1) % NSTACK;
    for (int t = 0; t < T; t++) {
        float pop = s_pop[t];
        float push = 1.0f - pop;
        float ptr_push = __shfl_sync(FULL, ptr, src_push);
        float ptr_pop = __shfl_sync(FULL, ptr, src_pop);
        float a = push * (1.0f - ptr_push) + pop * (1.0f - ptr);
        float c = push * ptr_push;
        float e = pop * (ZEROOFF * ptr);
        float mix = push * ptr_push + pop * ptr_pop;
        float pm = fmaxf(mix, 0.0f);
        float pw;
        if (fast5) {
            float p2 = pm * pm;
            pw = p2 * p2 * pm;
        } else {
            pw = powf(pm, sharp);
        }
        float s = active ? pw : 0.0f;
        #pragma unroll
        for (int o = 8; o > 0; o >>= 1) s += __shfl_xor_sync(FULL, s, o);
        float q = __fdividef(pw, s + EPSV);
        float* cf = cbase + (size_t)t * CSTRIDE;
        if (active) {
            cf[lane] = a;
            cf[12 + lane] = c;
            cf[24 + lane] = e;
            cf[36 + lane] = q;
        }
        if (lane == 0) cf[48] = pop;
        ptr = q;
    }
}

// ---------------------------------------------------------------------------
// K5: stack scan. block 128, float2 per thread, grid (V/256, B) = 256 blocks.
// Full-T coefficients staged in smem (53KB); x prefetched one step ahead.
// ---------------------------------------------------------------------------
__global__ void __launch_bounds__(128, 4)
k5_stack(const float* __restrict__ x, float* __restrict__ outs,
         float* __restrict__ tops, int T, int V) {
    extern __shared__ float s_c[];
    int b = blockIdx.y;
    const float4* cg = (const float4*)(g_coef + (size_t)b * T * CSTRIDE);
    float4* cs = (float4*)s_c;
    for (int i = threadIdx.x; i < T * (CSTRIDE / 4); i += blockDim.x) cs[i] = cg[i];
    __syncthreads();

    int col = blockIdx.x * blockDim.x + threadIdx.x;   // float2 column, 0..1023
    int stride2 = V >> 1;                               // 1024

    float stx[NSTACK], sty[NSTACK];
    #pragma unroll
    for (int n = 0; n < NSTACK; n++) { stx[n] = ZEROOFF; sty[n] = ZEROOFF; }

    const float2* xb = (const float2*)(x + (size_t)b * T * V) + col;
    float2* ob = (float2*)(outs + (size_t)b * T * V) + col;
    float2* tb = (float2*)(tops + (size_t)b * T * V) + col;

    float2 xv = xb[0];
    for (int t = 0; t < T; t++) {
        float2 xnext = (t + 1 < T) ? xb[(size_t)(t + 1) * stride2] : xv;
        const float4* cf4 = (const float4*)(s_c + t * CSTRIDE);
        float a[12], c[12], e[12], q[12];
        *(float4*)&a[0] = cf4[0]; *(float4*)&a[4] = cf4[1]; *(float4*)&a[8] = cf4[2];
        *(float4*)&c[0] = cf4[3]; *(float4*)&c[4] = cf4[4]; *(float4*)&c[8] = cf4[5];
        *(float4*)&e[0] = cf4[6]; *(float4*)&e[4] = cf4[7]; *(float4*)&e[8] = cf4[8];
        *(float4*)&q[0] = cf4[9]; *(float4*)&q[4] = cf4[10]; *(float4*)&q[8] = cf4[11];
        float pop = cf4[12].x;
        float topx = 0.f, topy = 0.f;
        #pragma unroll
        for (int n = 0; n < NSTACK; n++) {
            float wx = fmaf(c[n], xv.x, e[n]);
            float wy = fmaf(c[n], xv.y, e[n]);
            stx[n] = fmaf(a[n], stx[n], wx);
            sty[n] = fmaf(a[n], sty[n], wy);
            topx = fmaf(stx[n], q[n], topx);
            topy = fmaf(sty[n], q[n], topy);
        }
        float2 o2; o2.x = pop * topx; o2.y = pop * topy;
        float2 t2; t2.x = topx; t2.y = topy;
        ob[(size_t)t * stride2] = o2;
        tb[(size_t)t * stride2] = t2;
        xv = xnext;
    }
}

// ---------------------------------------------------------------------------
// Launch. Output layout: [outs BTV][latches BTV][pops BT][tops BTV]
// ---------------------------------------------------------------------------
extern "C" void kernel_launch(void* const* d_in, const int* in_sizes, int n_in,
                              void* d_out, int out_size) {
    const float* x = (const float*)d_in[0];
    const float* sp = (const float*)d_in[1];
    const float* shp = (const float*)d_in[2];
    const float* le = (const float*)d_in[3];
    const float* l0 = (const float*)d_in[4];

    int V = in_sizes[1];
    int B = in_sizes[4] / V;
    int T = in_sizes[0] / in_sizes[4];

    float* out = (float*)d_out;
    size_t btv = (size_t)B * T * V;
    float* outs = out;
    float* latches = out + btv;
    float* pops = out + 2 * btv;
    float* tops = out + 2 * btv + (size_t)B * T;

    static bool attr_set = false;
    if (!attr_set) {
        cudaFuncSetAttribute(k5_stack, cudaFuncAttributeMaxDynamicSharedMemorySize,
                             CSTRIDE * 256 * (int)sizeof(float) + 256);
        attr_set = true;
    }

    k0_norms<<<1, 256>>>(le, sp, V);
    k1_interp<<<B * T / 8, 256>>>(x, le, V);
    dim3 g2(4, B);
    k2_latch<<<g2, 128>>>(x, l0, sp, latches, T, V);
    k3b_pops<<<B * T / 256, 256>>>(pops, T);
    k4_ptr<<<B, 32>>>(pops, shp, T);
    dim3 g5(V / 256, B);
    k5_stack<<<g5, 128, T * CSTRIDE * sizeof(float)>>>(x, outs, tops, T, V);
}

// round 5
// speedup vs baseline: 1.6255x; 1.0151x over previous
#include <cuda_runtime.h>
#include <math.h>

#define NSTACK 12
#define ZEROOFF 0.001f
#define EPSV 1e-8f
#define CREC 52     // per-step coef record: a[0:12] c[12:24] e[24:36] q[36:48] pop[48], pad->52

// Fixed shapes (B=32, T=256, V=2048) for scratch sizing.
__device__ float g_norms[2];             // [0]=||latch_enable||, [1]=||should_pop||
__device__ float g_interp[32 * 256];
__device__ float g_partd[32 * 4 * 256];  // per (b, blk, t): partial sp.latch_{t-1}
__device__ float g_partn[32 * 4 * 256];  // per (b, blk, t): partial ||latch_{t-1}||^2

__device__ __forceinline__ float dot4(float4 a, float4 b) {
    return a.x * b.x + a.y * b.y + a.z * b.z + a.w * b.w;
}

// ---------------------------------------------------------------------------
// K0: norms of latch_enable and should_pop.
// ---------------------------------------------------------------------------
__global__ void k0_norms(const float* __restrict__ le, const float* __restrict__ sp, int V) {
    float a = 0.f, b = 0.f;
    int lane = threadIdx.x & 31;
    const float4* le4 = (const float4*)le;
    const float4* sp4 = (const float4*)sp;
    for (int i = threadIdx.x; i < V / 4; i += blockDim.x) {
        float4 l = le4[i], s = sp4[i];
        a += dot4(l, l);
        b += dot4(s, s);
    }
    #pragma unroll
    for (int o = 16; o > 0; o >>= 1) {
        a += __shfl_xor_sync(0xffffffffu, a, o);
        b += __shfl_xor_sync(0xffffffffu, b, o);
    }
    __shared__ float sa[32], sb[32];
    int w = threadIdx.x >> 5;
    if (lane == 0) { sa[w] = a; sb[w] = b; }
    __syncthreads();
    if (threadIdx.x == 0) {
        float ta = 0.f, tb = 0.f;
        for (int i = 0; i < (int)(blockDim.x >> 5); i++) { ta += sa[i]; tb += sb[i]; }
        g_norms[0] = sqrtf(ta);
        g_norms[1] = sqrtf(tb);
    }
}

// ---------------------------------------------------------------------------
// K1: interp[b,t] = cos(latch_enable, x[b,t]).  One WARP per row, MLP=8.
// ---------------------------------------------------------------------------
__global__ void k1_interp(const float* __restrict__ x, const float* __restrict__ le, int V) {
    int row = blockIdx.x * 8 + (threadIdx.x >> 5);
    int lane = threadIdx.x & 31;
    const float4* xp = (const float4*)(x + (size_t)row * V);
    const float4* le4 = (const float4*)le;
    float d = 0.f, n = 0.f;
    for (int i0 = lane; i0 < V / 4; i0 += 128) {
        float4 xv[4], l[4];
        #pragma unroll
        for (int j = 0; j < 4; j++) { xv[j] = xp[i0 + 32 * j]; l[j] = le4[i0 + 32 * j]; }
        #pragma unroll
        for (int j = 0; j < 4; j++) {
            d += dot4(l[j], xv[j]);
            n += dot4(xv[j], xv[j]);
        }
    }
    #pragma unroll
    for (int o = 16; o > 0; o >>= 1) {
        d += __shfl_xor_sync(0xffffffffu, d, o);
        n += __shfl_xor_sync(0xffffffffu, n, o);
    }
    if (lane == 0) {
        float nle = fmaxf(g_norms[0], EPSV);
        float nx = fmaxf(sqrtf(n), EPSV);
        g_interp[row] = d / (nle * nx);
    }
}

// ---------------------------------------------------------------------------
// K2: latch scan + fused pop partials; butterflies hoisted OUT of the
// recurrence (8 latch steps, then 16 interleaved independent reductions).
// grid (4, B), block 128.
// ---------------------------------------------------------------------------
__global__ void k2_latch(const float* __restrict__ x, const float* __restrict__ latch0,
                         const float* __restrict__ sp, float* __restrict__ latches,
                         int T, int V) {
    __shared__ float s_i[256];
    __shared__ float s_wd[256][4];
    __shared__ float s_wn[256][4];
    int b = blockIdx.y;
    int tid = threadIdx.x;
    int lane = tid & 31;
    int w = tid >> 5;
    int v4 = blockIdx.x * blockDim.x + tid;
    int stride4 = V >> 2;

    for (int t = tid; t < T; t += blockDim.x) s_i[t] = g_interp[b * T + t];
    __syncthreads();

    float4 sp4 = ((const float4*)sp)[v4];
    float4 latch = ((const float4*)(latch0 + (size_t)b * V))[v4];
    const float4* xp = (const float4*)(x + (size_t)b * T * V) + v4;
    float4* lp = (float4*)(latches + (size_t)b * T * V) + v4;

    // slot 0: stats of latch0 (for pop[0])
    {
        float d = dot4(sp4, latch);
        float n = dot4(latch, latch);
        #pragma unroll
        for (int o = 16; o > 0; o >>= 1) {
            d += __shfl_xor_sync(0xffffffffu, d, o);
            n += __shfl_xor_sync(0xffffffffu, n, o);
        }
        if (lane == 0) { s_wd[0][w] = d; s_wn[0][w] = n; }
    }

    for (int t0 = 0; t0 < T; t0 += 8) {
        float4 xs[8];
        #pragma unroll
        for (int j = 0; j < 8; j++) xs[j] = xp[(size_t)(t0 + j) * stride4];
        float d8[8], n8[8];
        #pragma unroll
        for (int j = 0; j < 8; j++) {
            float i = s_i[t0 + j];
            latch.x = fmaf(i, xs[j].x - latch.x, latch.x);
            latch.y = fmaf(i, xs[j].y - latch.y, latch.y);
            latch.z = fmaf(i, xs[j].z - latch.z, latch.z);
            latch.w = fmaf(i, xs[j].w - latch.w, latch.w);
            lp[(size_t)(t0 + j) * stride4] = latch;
            d8[j] = dot4(sp4, latch);
            n8[j] = dot4(latch, latch);
        }
        // 16 independent butterflies, interleaved for ILP
        #pragma unroll
        for (int o = 16; o > 0; o >>= 1) {
            #pragma unroll
            for (int j = 0; j < 8; j++) {
                d8[j] += __shfl_xor_sync(0xffffffffu, d8[j], o);
                n8[j] += __shfl_xor_sync(0xffffffffu, n8[j], o);
            }
        }
        if (lane == 0) {
            #pragma unroll
            for (int j = 0; j < 8; j++) {
                int t = t0 + j;
                if (t + 1 < T) { s_wd[t + 1][w] = d8[j]; s_wn[t + 1][w] = n8[j]; }
            }
        }
    }
    __syncthreads();
    int pbase = (b * 4 + blockIdx.x) * T;
    for (int t = tid; t < T; t += blockDim.x) {
        g_partd[pbase + t] = s_wd[t][0] + s_wd[t][1] + s_wd[t][2] + s_wd[t][3];
        g_partn[pbase + t] = s_wn[t][0] + s_wn[t][1] + s_wn[t][2] + s_wn[t][3];
    }
}

// ---------------------------------------------------------------------------
// K3b: finalize pop[b,t] = elu(cos) from the 4 per-block partials.
// ---------------------------------------------------------------------------
__global__ void k3b_pops(float* __restrict__ pops, int T) {
    int bt = blockIdx.x * blockDim.x + threadIdx.x;
    int b = bt / T;
    int t = bt - b * T;
    float d = 0.f, n = 0.f;
    #pragma unroll
    for (int blk = 0; blk < 4; blk++) {
        d += g_partd[(b * 4 + blk) * T + t];
        n += g_partn[(b * 4 + blk) * T + t];
    }
    float nsp = fmaxf(g_norms[1], EPSV);
    float nl = fmaxf(sqrtf(n), EPSV);
    float c = d / (nsp * nl);
    pops[bt] = (c > 0.0f) ? c : expm1f(c);
}

// ---------------------------------------------------------------------------
// Scan step (warp-level): advances ptr one step, writes coef record to buf.
// ---------------------------------------------------------------------------
__device__ __forceinline__ void scan_step(float& ptr, float pop, float sharp, bool fast5,
                                          int lane, bool active, int src_push, int src_pop,
                                          float* __restrict__ buf) {
    const unsigned FULL = 0xffffffffu;
    float push = 1.0f - pop;
    float ptr_push = __shfl_sync(FULL, ptr, src_push);
    float ptr_pop = __shfl_sync(FULL, ptr, src_pop);
    float a = push * (1.0f - ptr_push) + pop * (1.0f - ptr);
    float c = push * ptr_push;
    float e = pop * (ZEROOFF * ptr);
    float mix = push * ptr_push + pop * ptr_pop;
    float pm = fmaxf(mix, 0.0f);
    float pw;
    if (fast5) {
        float p2 = pm * pm;
        pw = p2 * p2 * pm;
    } else {
        pw = powf(pm, sharp);
    }
    float s = active ? pw : 0.0f;
    #pragma unroll
    for (int o = 8; o > 0; o >>= 1) s += __shfl_xor_sync(FULL, s, o);
    float q = __fdividef(pw, s + EPSV);
    if (active) {
        buf[lane] = a;
        buf[12 + lane] = c;
        buf[24 + lane] = e;
        buf[36 + lane] = q;
    }
    if (lane == 0) buf[48] = pop;
    ptr = q;
}

// ---------------------------------------------------------------------------
// K5: fused pointer-scan + stack scan. 5 warps/block: warp 4 produces coef
// records (double-buffered in smem) one step ahead; warps 0-3 consume them
// for 128 float2 columns. grid (8, B) = 256 blocks; tiny smem.
// ---------------------------------------------------------------------------
__global__ void __launch_bounds__(160)
k5_fused(const float* __restrict__ x, const float* __restrict__ pops,
         const float* __restrict__ sharp_ptr, float* __restrict__ outs,
         float* __restrict__ tops, int T, int V) {
    __shared__ float s_pop[256];
    __shared__ __align__(16) float s_coef[2][CREC];
    int b = blockIdx.y;
    int tid = threadIdx.x;
    int wid = tid >> 5;
    int lane = tid & 31;

    for (int i = tid; i < T; i += blockDim.x) s_pop[i] = pops[b * T + i];
    __syncthreads();

    // scan warp state
    float ptr = (lane == 0) ? 1.0f : 0.0f;
    float sharp = 0.f;
    bool fast5 = false, active = false;
    int src_push = 0, src_pop = 0;
    if (wid == 4) {
        sharp = sharp_ptr[0];
        fast5 = (sharp == 5.0f);
        active = lane < NSTACK;
        src_push = (lane + NSTACK - 1) % NSTACK;
        src_pop = (lane + 1) % NSTACK;
        scan_step(ptr, s_pop[0], sharp, fast5, lane, active, src_push, src_pop, s_coef[0]);
    }

    // stack warp state
    int stride2 = V >> 1;  // 1024
    float stx[NSTACK], sty[NSTACK];
    const float2 *xp = 0;
    float2 *op = 0, *tp = 0;
    float2 xv = make_float2(0.f, 0.f);
    if (wid < 4) {
        #pragma unroll
        for (int n = 0; n < NSTACK; n++) { stx[n] = ZEROOFF; sty[n] = ZEROOFF; }
        int col = blockIdx.x * 128 + wid * 32 + lane;  // float2 column
        xp = (const float2*)(x + (size_t)b * T * V) + col;
        op = (float2*)(outs + (size_t)b * T * V) + col;
        tp = (float2*)(tops + (size_t)b * T * V) + col;
        xv = *xp;
    }
    __syncthreads();

    for (int t = 0; t < T; t++) {
        if (wid < 4) {
            float2 xnext = (t + 1 < T) ? xp[stride2] : xv;
            const float4* cf4 = (const float4*)s_coef[t & 1];
            float a[12], c[12], e[12], q[12];
            *(float4*)&a[0] = cf4[0]; *(float4*)&a[4] = cf4[1]; *(float4*)&a[8] = cf4[2];
            *(float4*)&c[0] = cf4[3]; *(float4*)&c[4] = cf4[4]; *(float4*)&c[8] = cf4[5];
            *(float4*)&e[0] = cf4[6]; *(float4*)&e[4] = cf4[7]; *(float4*)&e[8] = cf4[8];
            *(float4*)&q[0] = cf4[9]; *(float4*)&q[4] = cf4[10]; *(float4*)&q[8] = cf4[11];
            float pop = cf4[12].x;
            float topx = 0.f, topy = 0.f;
            #pragma unroll
            for (int n = 0; n < NSTACK; n++) {
                float wx = fmaf(c[n], xv.x, e[n]);
                float wy = fmaf(c[n], xv.y, e[n]);
                stx[n] = fmaf(a[n], stx[n], wx);
                sty[n] = fmaf(a[n], sty[n], wy);
                topx = fmaf(stx[n], q[n], topx);
                topy = fmaf(sty[n], q[n], topy);
            }
            float2 o2; o2.x = pop * topx; o2.y = pop * topy;
            float2 t2; t2.x = topx; t2.y = topy;
            *op = o2;
            *tp = t2;
            xv = xnext;
            xp += stride2; op += stride2; tp += stride2;
        } else {
            if (t + 1 < T)
                scan_step(ptr, s_pop[t + 1], sharp, fast5, lane, active, src_push, src_pop,
                          s_coef[(t + 1) & 1]);
        }
        __syncthreads();
    }
}

// ---------------------------------------------------------------------------
// Launch. Output layout: [outs BTV][latches BTV][pops BT][tops BTV]
// ---------------------------------------------------------------------------
extern "C" void kernel_launch(void* const* d_in, const int* in_sizes, int n_in,
                              void* d_out, int out_size) {
    const float* x = (const float*)d_in[0];
    const float* sp = (const float*)d_in[1];
    const float* shp = (const float*)d_in[2];
    const float* le = (const float*)d_in[3];
    const float* l0 = (const float*)d_in[4];

    int V = in_sizes[1];
    int B = in_sizes[4] / V;
    int T = in_sizes[0] / in_sizes[4];

    float* out = (float*)d_out;
    size_t btv = (size_t)B * T * V;
    float* outs = out;
    float* latches = out + btv;
    float* pops = out + 2 * btv;
    float* tops = out + 2 * btv + (size_t)B * T;

    k0_norms<<<1, 256>>>(le, sp, V);
    k1_interp<<<B * T / 8, 256>>>(x, le, V);
    dim3 g2(4, B);
    k2_latch<<<g2, 128>>>(x, l0, sp, latches, T, V);
    k3b_pops<<<B * T / 256, 256>>>(pops, T);
    dim3 g5(8, B);
    k5_fused<<<g5, 160>>>(x, pops, shp, outs, tops, T, V);
}